// round 1
// baseline (speedup 1.0000x reference)
#include <cuda_runtime.h>
#include <math.h>
#include <stdint.h>

#define EMBED 2048
#define HEADS 16
#define HD    128
#define DFF   8192
#define BATCH 2
#define SEQ   2048
#define TOKENS (BATCH*SEQ)   // 4096
#define LN_EPS 1e-5f

// ---------------- scratch (static device globals; no allocation) ----------------
__device__ float g_q [(size_t)TOKENS*EMBED];                 // [B,H,N,hd] packed
__device__ float g_k [(size_t)TOKENS*EMBED];
__device__ float g_v [(size_t)TOKENS*EMBED];
__device__ float g_s [(size_t)BATCH*HEADS*SEQ*SEQ];          // scores, 512 MB
__device__ float g_ao[(size_t)TOKENS*EMBED];                 // attention out [B,N,C]
__device__ float g_t1[(size_t)TOKENS*EMBED];                 // pre-LN temp
__device__ float g_h [(size_t)TOKENS*EMBED];                 // post-LN1
__device__ float g_f1[(size_t)TOKENS*DFF];                   // FFN hidden

// ---------------- GEMM ----------------
// C = epilogue(scale * A@B(^T) + bias [+ res])
// A: [M,K] row-major. B: NN -> [K,N] row-major ; NT -> [N,K] row-major.
// Batched via blockIdx.z with element strides.
enum { EP_PLAIN=0, EP_SPLITQKV=1, EP_MERGEHEADS=2, EP_RES=3, EP_GELU=4 };

template<int MODE, bool TB>
__global__ __launch_bounds__(256)
void gemm_kernel(const float* __restrict__ A, const float* __restrict__ Bm,
                 const float* __restrict__ bias, const float* __restrict__ res,
                 float* __restrict__ C,
                 int M, int N, int K, float scale,
                 long strideA, long strideB, long strideC)
{
    const int BK = 8;
    __shared__ float As[BK][128];
    __shared__ float Bs[BK][128];

    const int bz = blockIdx.z;
    const float* Ab = A  + (size_t)bz * strideA;
    const float* Bb = Bm + (size_t)bz * strideB;

    const int bm = blockIdx.y * 128;
    const int bn = blockIdx.x * 128;
    const int tid = threadIdx.x;
    const int tx = tid & 15;        // 0..15  -> col group (8 cols)
    const int ty = tid >> 4;        // 0..15  -> row group (8 rows)

    // A tile load mapping: 128 rows x 8 cols, float4 per thread
    const int arow = tid >> 1;
    const int acol = (tid & 1) * 4;

    float acc[8][8];
    #pragma unroll
    for (int i = 0; i < 8; i++)
        #pragma unroll
        for (int j = 0; j < 8; j++) acc[i][j] = 0.f;

    for (int k0 = 0; k0 < K; k0 += BK) {
        // ---- stage A (transposed into As[k][m]) ----
        float4 av = *(const float4*)&Ab[(size_t)(bm + arow) * K + k0 + acol];
        As[acol+0][arow] = av.x; As[acol+1][arow] = av.y;
        As[acol+2][arow] = av.z; As[acol+3][arow] = av.w;

        // ---- stage B ----
        if (!TB) {
            const int br = tid >> 5;            // 0..7 (k)
            const int bc = (tid & 31) * 4;      // 0..124 (n)
            float4 bv = *(const float4*)&Bb[(size_t)(k0 + br) * N + bn + bc];
            *(float4*)&Bs[br][bc] = bv;
        } else {
            const int br = tid >> 1;            // 0..127 (n)
            const int bc = (tid & 1) * 4;       // 0..4   (k)
            float4 bv = *(const float4*)&Bb[(size_t)(bn + br) * K + k0 + bc];
            Bs[bc+0][br] = bv.x; Bs[bc+1][br] = bv.y;
            Bs[bc+2][br] = bv.z; Bs[bc+3][br] = bv.w;
        }
        __syncthreads();

        #pragma unroll
        for (int kk = 0; kk < BK; kk++) {
            float ar[8], brg[8];
            *(float4*)&ar[0]  = *(const float4*)&As[kk][ty*8];
            *(float4*)&ar[4]  = *(const float4*)&As[kk][ty*8+4];
            *(float4*)&brg[0] = *(const float4*)&Bs[kk][tx*8];
            *(float4*)&brg[4] = *(const float4*)&Bs[kk][tx*8+4];
            #pragma unroll
            for (int i = 0; i < 8; i++)
                #pragma unroll
                for (int j = 0; j < 8; j++)
                    acc[i][j] = fmaf(ar[i], brg[j], acc[i][j]);
        }
        __syncthreads();
    }

    // ---- epilogue ----
    #pragma unroll
    for (int i = 0; i < 8; i++) {
        const int m = bm + ty*8 + i;
        #pragma unroll
        for (int j = 0; j < 8; j++) {
            const int n = bn + tx*8 + j;
            float v = acc[i][j] * scale;
            if (MODE != EP_MERGEHEADS && bias) v += bias[n];

            if (MODE == EP_PLAIN) {
                float* Cb = C + (size_t)bz * strideC;
                Cb[(size_t)m * N + n] = v;
            } else if (MODE == EP_SPLITQKV) {
                // m = global token (b*SEQ + nn), n = h*HD + d  -> [B,H,N,hd]
                const int b  = m / SEQ, nn = m - b*SEQ;
                const int h  = n / HD,  d  = n - h*HD;
                g_q[0]; // no-op to keep template generic
                C[(((size_t)(b*HEADS + h))*SEQ + nn)*HD + d] = v;
            } else if (MODE == EP_MERGEHEADS) {
                // bz = b*HEADS + h ; m = seq pos ; n = dim within head
                const int b = bz / HEADS, h = bz - b*HEADS;
                C[((size_t)(b*SEQ + m))*EMBED + h*HD + n] = v;
            } else if (MODE == EP_RES) {
                v += res[(size_t)m * N + n];
                C[(size_t)m * N + n] = v;
            } else { // EP_GELU (exact)
                v = 0.5f * v * (1.f + erff(v * 0.70710678118654752f));
                C[(size_t)m * N + n] = v;
            }
        }
    }
}

// ---------------- softmax over last dim (rows of SEQ) ----------------
__global__ __launch_bounds__(256)
void softmax_kernel(float* __restrict__ S)
{
    __shared__ float red[256];
    const size_t row = blockIdx.x;
    float* p = S + row * (size_t)SEQ;
    const int tid = threadIdx.x;

    float v[8];
    float lmax = -1e30f;
    #pragma unroll
    for (int i = 0; i < 8; i++) { v[i] = p[tid + i*256]; lmax = fmaxf(lmax, v[i]); }
    red[tid] = lmax; __syncthreads();
    for (int s = 128; s > 0; s >>= 1) { if (tid < s) red[tid] = fmaxf(red[tid], red[tid+s]); __syncthreads(); }
    const float m = red[0]; __syncthreads();

    float lsum = 0.f;
    #pragma unroll
    for (int i = 0; i < 8; i++) { v[i] = expf(v[i] - m); lsum += v[i]; }
    red[tid] = lsum; __syncthreads();
    for (int s = 128; s > 0; s >>= 1) { if (tid < s) red[tid] += red[tid+s]; __syncthreads(); }
    const float inv = 1.f / red[0];

    #pragma unroll
    for (int i = 0; i < 8; i++) p[tid + i*256] = v[i] * inv;
}

// ---------------- LayerNorm over last dim (rows of EMBED) ----------------
__global__ __launch_bounds__(256)
void ln_kernel(const float* __restrict__ in, const float* __restrict__ g,
               const float* __restrict__ b, float* __restrict__ out)
{
    __shared__ float r1[256], r2[256];
    const size_t row = blockIdx.x;
    const float* p = in + row * (size_t)EMBED;
    const int tid = threadIdx.x;

    float v[8];
    float s = 0.f, ss = 0.f;
    #pragma unroll
    for (int i = 0; i < 8; i++) { v[i] = p[tid + i*256]; s += v[i]; ss += v[i]*v[i]; }
    r1[tid] = s; r2[tid] = ss; __syncthreads();
    for (int st = 128; st > 0; st >>= 1) {
        if (tid < st) { r1[tid] += r1[tid+st]; r2[tid] += r2[tid+st]; }
        __syncthreads();
    }
    const float mu  = r1[0] * (1.f / EMBED);
    const float var = r2[0] * (1.f / EMBED) - mu * mu;
    const float rs  = rsqrtf(var + LN_EPS);

    float* o = out + row * (size_t)EMBED;
    #pragma unroll
    for (int i = 0; i < 8; i++) {
        const int c = tid + i*256;
        o[c] = (v[i] - mu) * rs * g[c] + b[c];
    }
}

// ---------------- launch ----------------
extern "C" void kernel_launch(void* const* d_in, const int* in_sizes, int n_in,
                              void* d_out, int out_size)
{
    const float* x   = (const float*)d_in[0];
    const float* Wq  = (const float*)d_in[1];
    const float* bq  = (const float*)d_in[2];
    const float* Wk  = (const float*)d_in[3];
    const float* bk  = (const float*)d_in[4];
    const float* Wv  = (const float*)d_in[5];
    const float* bv  = (const float*)d_in[6];
    const float* Wo  = (const float*)d_in[7];
    const float* bo  = (const float*)d_in[8];
    const float* g1  = (const float*)d_in[9];
    const float* b1  = (const float*)d_in[10];
    const float* g2  = (const float*)d_in[11];
    const float* b2  = (const float*)d_in[12];
    const float* W1  = (const float*)d_in[13];
    const float* bf1 = (const float*)d_in[14];
    const float* W2  = (const float*)d_in[15];
    const float* bf2 = (const float*)d_in[16];
    float* out = (float*)d_out;

    float *q, *k, *v, *s, *ao, *t1, *h, *f1;
    cudaGetSymbolAddress((void**)&q,  g_q);
    cudaGetSymbolAddress((void**)&k,  g_k);
    cudaGetSymbolAddress((void**)&v,  g_v);
    cudaGetSymbolAddress((void**)&s,  g_s);
    cudaGetSymbolAddress((void**)&ao, g_ao);
    cudaGetSymbolAddress((void**)&t1, g_t1);
    cudaGetSymbolAddress((void**)&h,  g_h);
    cudaGetSymbolAddress((void**)&f1, g_f1);

    const float att_scale = 0.08838834764831845f; // 1/sqrt(128)

    // QKV projections -> split-heads layout [B,H,N,hd]
    dim3 gQKV(EMBED/128, TOKENS/128, 1);
    gemm_kernel<EP_SPLITQKV,false><<<gQKV, 256>>>(x, Wq, bq, nullptr, q, TOKENS, EMBED, EMBED, 1.f, 0, 0, 0);
    gemm_kernel<EP_SPLITQKV,false><<<gQKV, 256>>>(x, Wk, bk, nullptr, k, TOKENS, EMBED, EMBED, 1.f, 0, 0, 0);
    gemm_kernel<EP_SPLITQKV,false><<<gQKV, 256>>>(x, Wv, bv, nullptr, v, TOKENS, EMBED, EMBED, 1.f, 0, 0, 0);

    // scores = scale * Q @ K^T  (batched over B*H)
    dim3 gS(SEQ/128, SEQ/128, BATCH*HEADS);
    gemm_kernel<EP_PLAIN,true><<<gS, 256>>>(q, k, nullptr, nullptr, s,
                                            SEQ, SEQ, HD, att_scale,
                                            (long)SEQ*HD, (long)SEQ*HD, (long)SEQ*SEQ);

    // softmax over rows
    softmax_kernel<<<BATCH*HEADS*SEQ, 256>>>(s);

    // O = S @ V  -> merge heads into [B,N,C]
    dim3 gPV(HD/128, SEQ/128, BATCH*HEADS);
    gemm_kernel<EP_MERGEHEADS,false><<<gPV, 256>>>(s, v, nullptr, nullptr, ao,
                                                   SEQ, HD, SEQ, 1.f,
                                                   (long)SEQ*SEQ, (long)SEQ*HD, 0);

    // out-proj + residual; then LN1
    dim3 gWo(EMBED/128, TOKENS/128, 1);
    gemm_kernel<EP_RES,false><<<gWo, 256>>>(ao, Wo, bo, x, t1, TOKENS, EMBED, EMBED, 1.f, 0, 0, 0);
    ln_kernel<<<TOKENS, 256>>>(t1, g1, b1, h);

    // FFN
    dim3 gF1(DFF/128, TOKENS/128, 1);
    gemm_kernel<EP_GELU,false><<<gF1, 256>>>(h, W1, bf1, nullptr, f1, TOKENS, DFF, EMBED, 1.f, 0, 0, 0);
    dim3 gF2(EMBED/128, TOKENS/128, 1);
    gemm_kernel<EP_RES,false><<<gF2, 256>>>(f1, W2, bf2, h, t1, TOKENS, EMBED, DFF, 1.f, 0, 0, 0);

    // LN2 -> final output
    ln_kernel<<<TOKENS, 256>>>(t1, g2, b2, out);
}

// round 2
// speedup vs baseline: 1.6110x; 1.6110x over previous
#include <cuda_runtime.h>
#include <cuda_bf16.h>
#include <math.h>
#include <stdint.h>

#define EMBED 2048
#define HEADS 16
#define HD    128
#define DFF   8192
#define BATCH 2
#define SEQ   2048
#define TOKENS (BATCH*SEQ)   // 4096
#define LN_EPS 1e-5f

// ---------------- scratch (static device globals; no allocation) ----------------
__device__ float g_q [(size_t)TOKENS*EMBED];                    // [B,H,N,hd] fp32
__device__ __nv_bfloat16 g_khi[(size_t)TOKENS*EMBED];           // [B,H,N,hd]
__device__ __nv_bfloat16 g_klo[(size_t)TOKENS*EMBED];
__device__ __nv_bfloat16 g_vthi[(size_t)TOKENS*EMBED];          // [B,H,hd,N]
__device__ __nv_bfloat16 g_vtlo[(size_t)TOKENS*EMBED];
__device__ float g_s [(size_t)BATCH*HEADS*SEQ*SEQ];             // scores fp32
__device__ float g_ao[(size_t)TOKENS*EMBED];
__device__ float g_t1[(size_t)TOKENS*EMBED];
__device__ float g_h [(size_t)TOKENS*EMBED];
__device__ float g_f1[(size_t)TOKENS*DFF];
// transposed, hi/lo-split weights  [N][K]
__device__ __nv_bfloat16 g_wqT_hi[(size_t)EMBED*EMBED], g_wqT_lo[(size_t)EMBED*EMBED];
__device__ __nv_bfloat16 g_wkT_hi[(size_t)EMBED*EMBED], g_wkT_lo[(size_t)EMBED*EMBED];
__device__ __nv_bfloat16 g_wvT_hi[(size_t)EMBED*EMBED], g_wvT_lo[(size_t)EMBED*EMBED];
__device__ __nv_bfloat16 g_woT_hi[(size_t)EMBED*EMBED], g_woT_lo[(size_t)EMBED*EMBED];
__device__ __nv_bfloat16 g_w1T_hi[(size_t)EMBED*DFF],   g_w1T_lo[(size_t)EMBED*DFF];
__device__ __nv_bfloat16 g_w2T_hi[(size_t)EMBED*DFF],   g_w2T_lo[(size_t)EMBED*DFF];

// ---------------- helpers ----------------
__device__ __forceinline__ void cvt2(float a, float b, unsigned &h, unsigned &l) {
    __nv_bfloat16 ha = __float2bfloat16(a), hb = __float2bfloat16(b);
    float ra = a - __bfloat162float(ha);
    float rb = b - __bfloat162float(hb);
    __nv_bfloat16 la = __float2bfloat16(ra), lb = __float2bfloat16(rb);
    h = ((unsigned)__bfloat16_as_ushort(hb) << 16) | (unsigned)__bfloat16_as_ushort(ha);
    l = ((unsigned)__bfloat16_as_ushort(lb) << 16) | (unsigned)__bfloat16_as_ushort(la);
}

__device__ __forceinline__ void cp_async16(void* dst_smem, const void* src) {
    unsigned s = (unsigned)__cvta_generic_to_shared(dst_smem);
    asm volatile("cp.async.cg.shared.global [%0], [%1], 16;\n" :: "r"(s), "l"(src));
}
__device__ __forceinline__ void cp_commit() { asm volatile("cp.async.commit_group;\n"); }
template<int Ngrp> __device__ __forceinline__ void cp_wait() {
    asm volatile("cp.async.wait_group %0;\n" :: "n"(Ngrp));
}

__device__ __forceinline__ void mma16816(float* c, const unsigned* a, const unsigned* b) {
    asm volatile(
        "mma.sync.aligned.m16n8k16.row.col.f32.bf16.bf16.f32 "
        "{%0,%1,%2,%3}, {%4,%5,%6,%7}, {%8,%9}, {%0,%1,%2,%3};\n"
        : "+f"(c[0]), "+f"(c[1]), "+f"(c[2]), "+f"(c[3])
        : "r"(a[0]), "r"(a[1]), "r"(a[2]), "r"(a[3]), "r"(b[0]), "r"(b[1]));
}

// ---------------- weight transpose + hi/lo split: in[R][C] -> out[C][R] ----------------
__global__ __launch_bounds__(256)
void transpose_convert(const float* __restrict__ in,
                       __nv_bfloat16* __restrict__ hi, __nv_bfloat16* __restrict__ lo,
                       int R, int C)
{
    __shared__ float t[32][33];
    const int c0 = blockIdx.x * 32, r0 = blockIdx.y * 32;
    const int tx = threadIdx.x & 31, ty = threadIdx.x >> 5;   // 32 x 8
    #pragma unroll
    for (int i = 0; i < 32; i += 8)
        t[ty + i][tx] = in[(size_t)(r0 + ty + i) * C + c0 + tx];
    __syncthreads();
    #pragma unroll
    for (int i = 0; i < 32; i += 8) {
        float v = t[tx][ty + i];
        __nv_bfloat16 h = __float2bfloat16(v);
        float rem = v - __bfloat162float(h);
        size_t o = (size_t)(c0 + ty + i) * R + r0 + tx;
        hi[o] = h; lo[o] = __float2bfloat16(rem);
    }
}

// ---------------- bf16x3 tensor-core GEMM ----------------
// C = epilogue(scale * A @ B^T + bias [+ res]),  A fp32 [M,K], B bf16 hi/lo [N,K]
enum { EP_PLAIN=0, EP_Q=1, EP_KBF=2, EP_VT=3, EP_MERGE=4, EP_RES=5, EP_GELU=6 };

#define LDA 40                      // halves per smem row (pad 8) - bank-conflict free
#define STG (128*LDA)               // halves per buffer

template<int MODE>
__global__ __launch_bounds__(256)
void mma_gemm(const float* __restrict__ A,
              const __nv_bfloat16* __restrict__ Bhi, const __nv_bfloat16* __restrict__ Blo,
              const float* __restrict__ bias, const float* __restrict__ res,
              void* __restrict__ O0, void* __restrict__ O1,
              int M, int N, int K, float scale, long sA, long sB)
{
    extern __shared__ __nv_bfloat16 sm[];
    __nv_bfloat16* Ah[2]; __nv_bfloat16* Al[2];
    __nv_bfloat16* Bh[2]; __nv_bfloat16* Bl[2];
    #pragma unroll
    for (int s = 0; s < 2; s++) {
        Ah[s] = sm + (size_t)s*4*STG;
        Al[s] = Ah[s] + STG;
        Bh[s] = Ah[s] + 2*STG;
        Bl[s] = Ah[s] + 3*STG;
    }

    const int bz = blockIdx.z;
    const float* Ab = A + (size_t)bz * sA;
    const __nv_bfloat16* Bhib = Bhi + (size_t)bz * sB;
    const __nv_bfloat16* Blob = Blo + (size_t)bz * sB;
    const int bm = blockIdx.y * 128;
    const int bn = blockIdx.x * 128;
    const int tid  = threadIdx.x;
    const int lane = tid & 31;
    const int warp = tid >> 5;
    const int wm = warp >> 2;   // 0..1
    const int wn = warp & 3;    // 0..3

    float acc[4][4][4];
    #pragma unroll
    for (int i = 0; i < 4; i++)
        #pragma unroll
        for (int j = 0; j < 4; j++)
            #pragma unroll
            for (int p = 0; p < 4; p++) acc[i][j][p] = 0.f;

    // A LDG mapping: 128 rows x 32 cols fp32, 4 float4 per thread
    const int am = tid >> 1;             // 0..127
    const int ak = (tid & 1) * 16;       // 0 or 16
    // B cp.async mapping: 128 rows x 32 halves, 16B chunks
    const int bnr = tid >> 2;            // 0..63
    const int bkc = (tid & 3) * 8;       // halves

    float4 areg[4];

    const int NIT = K >> 5;

    // ---- prologue: stage 0 ----
    {
        #pragma unroll
        for (int j = 0; j < 4; j++)
            areg[j] = *(const float4*)&Ab[(size_t)(bm + am) * K + ak + j*4];
        #pragma unroll
        for (int r = 0; r < 128; r += 64) {
            cp_async16(&Bh[0][(bnr + r) * LDA + bkc], &Bhib[(size_t)(bn + bnr + r) * K + bkc]);
            cp_async16(&Bl[0][(bnr + r) * LDA + bkc], &Blob[(size_t)(bn + bnr + r) * K + bkc]);
        }
        cp_commit();
        #pragma unroll
        for (int j = 0; j < 4; j++) {
            unsigned h0, l0, h1, l1;
            cvt2(areg[j].x, areg[j].y, h0, l0);
            cvt2(areg[j].z, areg[j].w, h1, l1);
            *(unsigned*)&Ah[0][am * LDA + ak + j*4]     = h0;
            *(unsigned*)&Ah[0][am * LDA + ak + j*4 + 2] = h1;
            *(unsigned*)&Al[0][am * LDA + ak + j*4]     = l0;
            *(unsigned*)&Al[0][am * LDA + ak + j*4 + 2] = l1;
        }
    }

    for (int it = 0; it < NIT; it++) {
        const int cur = it & 1, nxt = cur ^ 1;
        const bool more = (it + 1 < NIT);
        if (more) {
            const int k0 = (it + 1) << 5;
            #pragma unroll
            for (int j = 0; j < 4; j++)
                areg[j] = *(const float4*)&Ab[(size_t)(bm + am) * K + k0 + ak + j*4];
            #pragma unroll
            for (int r = 0; r < 128; r += 64) {
                cp_async16(&Bh[nxt][(bnr + r) * LDA + bkc], &Bhib[(size_t)(bn + bnr + r) * K + k0 + bkc]);
                cp_async16(&Bl[nxt][(bnr + r) * LDA + bkc], &Blob[(size_t)(bn + bnr + r) * K + k0 + bkc]);
            }
            cp_commit();
            cp_wait<1>();
        } else {
            cp_wait<0>();
        }
        __syncthreads();

        // ---- compute on stage cur ----
        #pragma unroll
        for (int ks = 0; ks < 2; ks++) {
            const int kb = ks * 16 + (lane & 3) * 2;
            unsigned ah[4][4], al[4][4];
            #pragma unroll
            for (int mt = 0; mt < 4; mt++) {
                const int r = wm * 64 + mt * 16 + (lane >> 2);
                const __nv_bfloat16* ph = Ah[cur] + r * LDA;
                const __nv_bfloat16* pl = Al[cur] + r * LDA;
                ah[mt][0] = *(const unsigned*)&ph[kb];
                ah[mt][1] = *(const unsigned*)&ph[8*LDA + kb];
                ah[mt][2] = *(const unsigned*)&ph[kb + 8];
                ah[mt][3] = *(const unsigned*)&ph[8*LDA + kb + 8];
                al[mt][0] = *(const unsigned*)&pl[kb];
                al[mt][1] = *(const unsigned*)&pl[8*LDA + kb];
                al[mt][2] = *(const unsigned*)&pl[kb + 8];
                al[mt][3] = *(const unsigned*)&pl[8*LDA + kb + 8];
            }
            unsigned bh[4][2], bl[4][2];
            #pragma unroll
            for (int nt = 0; nt < 4; nt++) {
                const int r = wn * 32 + nt * 8 + (lane >> 2);
                bh[nt][0] = *(const unsigned*)&Bh[cur][r * LDA + kb];
                bh[nt][1] = *(const unsigned*)&Bh[cur][r * LDA + kb + 8];
                bl[nt][0] = *(const unsigned*)&Bl[cur][r * LDA + kb];
                bl[nt][1] = *(const unsigned*)&Bl[cur][r * LDA + kb + 8];
            }
            #pragma unroll
            for (int mt = 0; mt < 4; mt++)
                #pragma unroll
                for (int nt = 0; nt < 4; nt++) {
                    mma16816(acc[mt][nt], ah[mt], bh[nt]);
                    mma16816(acc[mt][nt], ah[mt], bl[nt]);
                    mma16816(acc[mt][nt], al[mt], bh[nt]);
                }
        }
        __syncthreads();

        if (more) {
            #pragma unroll
            for (int j = 0; j < 4; j++) {
                unsigned h0, l0, h1, l1;
                cvt2(areg[j].x, areg[j].y, h0, l0);
                cvt2(areg[j].z, areg[j].w, h1, l1);
                *(unsigned*)&Ah[nxt][am * LDA + ak + j*4]     = h0;
                *(unsigned*)&Ah[nxt][am * LDA + ak + j*4 + 2] = h1;
                *(unsigned*)&Al[nxt][am * LDA + ak + j*4]     = l0;
                *(unsigned*)&Al[nxt][am * LDA + ak + j*4 + 2] = l1;
            }
        }
    }

    // ---- epilogue ----
    #pragma unroll
    for (int mt = 0; mt < 4; mt++) {
        const int m0 = bm + wm * 64 + mt * 16 + (lane >> 2);
        #pragma unroll
        for (int nt = 0; nt < 4; nt++) {
            const int n0 = bn + wn * 32 + nt * 8 + (lane & 3) * 2;
            #pragma unroll
            for (int i = 0; i < 4; i++) {
                const int m = m0 + ((i >= 2) ? 8 : 0);
                const int n = n0 + (i & 1);
                float v = acc[mt][nt][i] * scale;

                if (MODE == EP_PLAIN) {
                    ((float*)O0)[(size_t)bz * M * N + (size_t)m * N + n] = v;
                } else if (MODE == EP_Q) {
                    v += bias[n];
                    const int b = m >> 11, nn = m & (SEQ-1);
                    const int h = n >> 7,  d  = n & (HD-1);
                    ((float*)O0)[(((size_t)(b*HEADS + h))*SEQ + nn)*HD + d] = v;
                } else if (MODE == EP_KBF) {
                    v += bias[n];
                    const int b = m >> 11, nn = m & (SEQ-1);
                    const int h = n >> 7,  d  = n & (HD-1);
                    const size_t o = (((size_t)(b*HEADS + h))*SEQ + nn)*HD + d;
                    __nv_bfloat16 hi = __float2bfloat16(v);
                    ((__nv_bfloat16*)O0)[o] = hi;
                    ((__nv_bfloat16*)O1)[o] = __float2bfloat16(v - __bfloat162float(hi));
                } else if (MODE == EP_VT) {
                    v += bias[n];
                    const int b = m >> 11, nn = m & (SEQ-1);
                    const int h = n >> 7,  d  = n & (HD-1);
                    const size_t o = (((size_t)(b*HEADS + h))*HD + d)*SEQ + nn;
                    __nv_bfloat16 hi = __float2bfloat16(v);
                    ((__nv_bfloat16*)O0)[o] = hi;
                    ((__nv_bfloat16*)O1)[o] = __float2bfloat16(v - __bfloat162float(hi));
                } else if (MODE == EP_MERGE) {
                    const int b = bz / HEADS, h = bz - b*HEADS;
                    ((float*)O0)[((size_t)(b*SEQ + m))*EMBED + h*HD + n] = v;
                } else if (MODE == EP_RES) {
                    v += bias[n] + res[(size_t)m * N + n];
                    ((float*)O0)[(size_t)m * N + n] = v;
                } else { // EP_GELU
                    v += bias[n];
                    v = 0.5f * v * (1.f + erff(v * 0.70710678118654752f));
                    ((float*)O0)[(size_t)m * N + n] = v;
                }
            }
        }
    }
}

// ---------------- softmax over last dim (rows of SEQ) ----------------
__global__ __launch_bounds__(256)
void softmax_kernel(float* __restrict__ S)
{
    __shared__ float red[256];
    const size_t row = blockIdx.x;
    float* p = S + row * (size_t)SEQ;
    const int tid = threadIdx.x;

    float v[8];
    float lmax = -1e30f;
    #pragma unroll
    for (int i = 0; i < 8; i++) { v[i] = p[tid + i*256]; lmax = fmaxf(lmax, v[i]); }
    red[tid] = lmax; __syncthreads();
    for (int s = 128; s > 0; s >>= 1) { if (tid < s) red[tid] = fmaxf(red[tid], red[tid+s]); __syncthreads(); }
    const float m = red[0]; __syncthreads();

    float lsum = 0.f;
    #pragma unroll
    for (int i = 0; i < 8; i++) { v[i] = expf(v[i] - m); lsum += v[i]; }
    red[tid] = lsum; __syncthreads();
    for (int s = 128; s > 0; s >>= 1) { if (tid < s) red[tid] += red[tid+s]; __syncthreads(); }
    const float inv = 1.f / red[0];

    #pragma unroll
    for (int i = 0; i < 8; i++) p[tid + i*256] = v[i] * inv;
}

// ---------------- LayerNorm over last dim (rows of EMBED) ----------------
__global__ __launch_bounds__(256)
void ln_kernel(const float* __restrict__ in, const float* __restrict__ g,
               const float* __restrict__ b, float* __restrict__ out)
{
    __shared__ float r1[256], r2[256];
    const size_t row = blockIdx.x;
    const float* p = in + row * (size_t)EMBED;
    const int tid = threadIdx.x;

    float v[8];
    float s = 0.f, ss = 0.f;
    #pragma unroll
    for (int i = 0; i < 8; i++) { v[i] = p[tid + i*256]; s += v[i]; ss += v[i]*v[i]; }
    r1[tid] = s; r2[tid] = ss; __syncthreads();
    for (int st = 128; st > 0; st >>= 1) {
        if (tid < st) { r1[tid] += r1[tid+st]; r2[tid] += r2[tid+st]; }
        __syncthreads();
    }
    const float mu  = r1[0] * (1.f / EMBED);
    const float var = r2[0] * (1.f / EMBED) - mu * mu;
    const float rs  = rsqrtf(var + LN_EPS);

    float* o = out + row * (size_t)EMBED;
    #pragma unroll
    for (int i = 0; i < 8; i++) {
        const int c = tid + i*256;
        o[c] = (v[i] - mu) * rs * g[c] + b[c];
    }
}

// ---------------- launch ----------------
#define SMEM_BYTES (2*4*STG*2)   // 81920

extern "C" void kernel_launch(void* const* d_in, const int* in_sizes, int n_in,
                              void* d_out, int out_size)
{
    const float* x   = (const float*)d_in[0];
    const float* Wq  = (const float*)d_in[1];
    const float* bq  = (const float*)d_in[2];
    const float* Wk  = (const float*)d_in[3];
    const float* bk  = (const float*)d_in[4];
    const float* Wv  = (const float*)d_in[5];
    const float* bv  = (const float*)d_in[6];
    const float* Wo  = (const float*)d_in[7];
    const float* bo  = (const float*)d_in[8];
    const float* g1  = (const float*)d_in[9];
    const float* b1  = (const float*)d_in[10];
    const float* g2  = (const float*)d_in[11];
    const float* b2  = (const float*)d_in[12];
    const float* W1  = (const float*)d_in[13];
    const float* bf1 = (const float*)d_in[14];
    const float* W2  = (const float*)d_in[15];
    const float* bf2 = (const float*)d_in[16];
    float* out = (float*)d_out;

    float *q, *s, *ao, *t1, *h, *f1;
    __nv_bfloat16 *khi, *klo, *vthi, *vtlo;
    __nv_bfloat16 *wqh,*wql,*wkh,*wkl,*wvh,*wvl,*woh,*wol,*w1h,*w1l,*w2h,*w2l;
    cudaGetSymbolAddress((void**)&q,   g_q);
    cudaGetSymbolAddress((void**)&khi, g_khi);
    cudaGetSymbolAddress((void**)&klo, g_klo);
    cudaGetSymbolAddress((void**)&vthi,g_vthi);
    cudaGetSymbolAddress((void**)&vtlo,g_vtlo);
    cudaGetSymbolAddress((void**)&s,   g_s);
    cudaGetSymbolAddress((void**)&ao,  g_ao);
    cudaGetSymbolAddress((void**)&t1,  g_t1);
    cudaGetSymbolAddress((void**)&h,   g_h);
    cudaGetSymbolAddress((void**)&f1,  g_f1);
    cudaGetSymbolAddress((void**)&wqh, g_wqT_hi); cudaGetSymbolAddress((void**)&wql, g_wqT_lo);
    cudaGetSymbolAddress((void**)&wkh, g_wkT_hi); cudaGetSymbolAddress((void**)&wkl, g_wkT_lo);
    cudaGetSymbolAddress((void**)&wvh, g_wvT_hi); cudaGetSymbolAddress((void**)&wvl, g_wvT_lo);
    cudaGetSymbolAddress((void**)&woh, g_woT_hi); cudaGetSymbolAddress((void**)&wol, g_woT_lo);
    cudaGetSymbolAddress((void**)&w1h, g_w1T_hi); cudaGetSymbolAddress((void**)&w1l, g_w1T_lo);
    cudaGetSymbolAddress((void**)&w2h, g_w2T_hi); cudaGetSymbolAddress((void**)&w2l, g_w2T_lo);

    cudaFuncSetAttribute(mma_gemm<EP_PLAIN>, cudaFuncAttributeMaxDynamicSharedMemorySize, SMEM_BYTES);
    cudaFuncSetAttribute(mma_gemm<EP_Q>,     cudaFuncAttributeMaxDynamicSharedMemorySize, SMEM_BYTES);
    cudaFuncSetAttribute(mma_gemm<EP_KBF>,   cudaFuncAttributeMaxDynamicSharedMemorySize, SMEM_BYTES);
    cudaFuncSetAttribute(mma_gemm<EP_VT>,    cudaFuncAttributeMaxDynamicSharedMemorySize, SMEM_BYTES);
    cudaFuncSetAttribute(mma_gemm<EP_MERGE>, cudaFuncAttributeMaxDynamicSharedMemorySize, SMEM_BYTES);
    cudaFuncSetAttribute(mma_gemm<EP_RES>,   cudaFuncAttributeMaxDynamicSharedMemorySize, SMEM_BYTES);
    cudaFuncSetAttribute(mma_gemm<EP_GELU>,  cudaFuncAttributeMaxDynamicSharedMemorySize, SMEM_BYTES);

    const float att_scale = 0.08838834764831845f; // 1/sqrt(128)

    // ---- weight prep: transpose + hi/lo split ----
    dim3 tb(256);
    transpose_convert<<<dim3(EMBED/32, EMBED/32), tb>>>(Wq, wqh, wql, EMBED, EMBED);
    transpose_convert<<<dim3(EMBED/32, EMBED/32), tb>>>(Wk, wkh, wkl, EMBED, EMBED);
    transpose_convert<<<dim3(EMBED/32, EMBED/32), tb>>>(Wv, wvh, wvl, EMBED, EMBED);
    transpose_convert<<<dim3(EMBED/32, EMBED/32), tb>>>(Wo, woh, wol, EMBED, EMBED);
    transpose_convert<<<dim3(DFF/32,   EMBED/32), tb>>>(W1, w1h, w1l, EMBED, DFF);
    transpose_convert<<<dim3(EMBED/32, DFF/32),   tb>>>(W2, w2h, w2l, DFF,   EMBED);

    // ---- QKV projections ----
    dim3 gQKV(EMBED/128, TOKENS/128, 1);
    mma_gemm<EP_Q>  <<<gQKV, 256, SMEM_BYTES>>>(x, wqh, wql, bq, nullptr, q,    nullptr, TOKENS, EMBED, EMBED, 1.f, 0, 0);
    mma_gemm<EP_KBF><<<gQKV, 256, SMEM_BYTES>>>(x, wkh, wkl, bk, nullptr, khi,  klo,     TOKENS, EMBED, EMBED, 1.f, 0, 0);
    mma_gemm<EP_VT> <<<gQKV, 256, SMEM_BYTES>>>(x, wvh, wvl, bv, nullptr, vthi, vtlo,    TOKENS, EMBED, EMBED, 1.f, 0, 0);

    // ---- scores = scale * Q @ K^T ----
    dim3 gS(SEQ/128, SEQ/128, BATCH*HEADS);
    mma_gemm<EP_PLAIN><<<gS, 256, SMEM_BYTES>>>(q, khi, klo, nullptr, nullptr, s, nullptr,
                                                SEQ, SEQ, HD, att_scale, (long)SEQ*HD, (long)SEQ*HD);

    softmax_kernel<<<BATCH*HEADS*SEQ, 256>>>(s);

    // ---- O = S @ V (V pre-transposed) ----
    dim3 gPV(HD/128, SEQ/128, BATCH*HEADS);
    mma_gemm<EP_MERGE><<<gPV, 256, SMEM_BYTES>>>(s, vthi, vtlo, nullptr, nullptr, ao, nullptr,
                                                 SEQ, HD, SEQ, 1.f, (long)SEQ*SEQ, (long)HD*SEQ);

    // ---- out-proj + residual, LN1 ----
    dim3 gWo(EMBED/128, TOKENS/128, 1);
    mma_gemm<EP_RES><<<gWo, 256, SMEM_BYTES>>>(ao, woh, wol, bo, x, t1, nullptr, TOKENS, EMBED, EMBED, 1.f, 0, 0);
    ln_kernel<<<TOKENS, 256>>>(t1, g1, b1, h);

    // ---- FFN ----
    dim3 gF1(DFF/128, TOKENS/128, 1);
    mma_gemm<EP_GELU><<<gF1, 256, SMEM_BYTES>>>(h, w1h, w1l, bf1, nullptr, f1, nullptr, TOKENS, DFF, EMBED, 1.f, 0, 0);
    dim3 gF2(EMBED/128, TOKENS/128, 1);
    mma_gemm<EP_RES><<<gF2, 256, SMEM_BYTES>>>(f1, w2h, w2l, bf2, h, t1, nullptr, TOKENS, EMBED, DFF, 1.f, 0, 0);

    ln_kernel<<<TOKENS, 256>>>(t1, g2, b2, out);
}

// round 5
// speedup vs baseline: 2.8310x; 1.7573x over previous
#include <cuda_runtime.h>
#include <cuda_bf16.h>
#include <math.h>
#include <stdint.h>

#define EMBED 2048
#define HEADS 16
#define HD    128
#define DFF   8192
#define BATCH 2
#define SEQ   2048
#define TOKENS (BATCH*SEQ)
#define LN_EPS 1e-5f

typedef __nv_bfloat16 bf16;

// ---------------- scratch ----------------
__device__ __align__(1024) bf16 g_xhi[(size_t)TOKENS*EMBED], g_xlo[(size_t)TOKENS*EMBED];
__device__ __align__(1024) bf16 g_qhi[(size_t)TOKENS*EMBED], g_qlo[(size_t)TOKENS*EMBED];
__device__ __align__(1024) bf16 g_khi[(size_t)TOKENS*EMBED], g_klo[(size_t)TOKENS*EMBED];
__device__ __align__(1024) bf16 g_vthi[(size_t)TOKENS*EMBED], g_vtlo[(size_t)TOKENS*EMBED];
__device__ __align__(1024) float g_s [(size_t)BATCH*HEADS*SEQ*SEQ];
__device__ __align__(1024) bf16 g_shi[(size_t)BATCH*HEADS*SEQ*SEQ], g_slo[(size_t)BATCH*HEADS*SEQ*SEQ];
__device__ __align__(1024) bf16 g_aohi[(size_t)TOKENS*EMBED], g_aolo[(size_t)TOKENS*EMBED];
__device__ __align__(1024) float g_t1[(size_t)TOKENS*EMBED];
__device__ __align__(1024) float g_h [(size_t)TOKENS*EMBED];
__device__ __align__(1024) bf16 g_hhi[(size_t)TOKENS*EMBED], g_hlo[(size_t)TOKENS*EMBED];
__device__ __align__(1024) bf16 g_f1hi[(size_t)TOKENS*DFF],  g_f1lo[(size_t)TOKENS*DFF];
__device__ __align__(1024) bf16 g_wqh[(size_t)EMBED*EMBED], g_wql[(size_t)EMBED*EMBED];
__device__ __align__(1024) bf16 g_wkh[(size_t)EMBED*EMBED], g_wkl[(size_t)EMBED*EMBED];
__device__ __align__(1024) bf16 g_wvh[(size_t)EMBED*EMBED], g_wvl[(size_t)EMBED*EMBED];
__device__ __align__(1024) bf16 g_woh[(size_t)EMBED*EMBED], g_wol[(size_t)EMBED*EMBED];
__device__ __align__(1024) bf16 g_w1h[(size_t)EMBED*DFF],   g_w1l[(size_t)EMBED*DFF];
__device__ __align__(1024) bf16 g_w2h[(size_t)EMBED*DFF],   g_w2l[(size_t)EMBED*DFF];

// ---------------- helpers ----------------
__device__ __forceinline__ uint32_t smem_u32(const void* p) {
    return (uint32_t)__cvta_generic_to_shared(p);
}
__device__ __forceinline__ void cp16(uint32_t dst, const void* src) {
    asm volatile("cp.async.cg.shared.global [%0], [%1], 16;\n" :: "r"(dst), "l"(src));
}
__device__ __forceinline__ void cp_commit() { asm volatile("cp.async.commit_group;\n"); }
template<int Ngrp> __device__ __forceinline__ void cp_wait() {
    asm volatile("cp.async.wait_group %0;\n" :: "n"(Ngrp));
}
__device__ __forceinline__ void ldsm4(uint32_t* r, uint32_t addr) {
    asm volatile("ldmatrix.sync.aligned.m8n8.x4.shared.b16 {%0,%1,%2,%3}, [%4];"
                 : "=r"(r[0]), "=r"(r[1]), "=r"(r[2]), "=r"(r[3]) : "r"(addr));
}
__device__ __forceinline__ void mma16816(float* c, const uint32_t* a, const uint32_t* b) {
    asm volatile(
        "mma.sync.aligned.m16n8k16.row.col.f32.bf16.bf16.f32 "
        "{%0,%1,%2,%3}, {%4,%5,%6,%7}, {%8,%9}, {%0,%1,%2,%3};\n"
        : "+f"(c[0]), "+f"(c[1]), "+f"(c[2]), "+f"(c[3])
        : "r"(a[0]), "r"(a[1]), "r"(a[2]), "r"(a[3]), "r"(b[0]), "r"(b[1]));
}
__device__ __forceinline__ uint32_t swz(uint32_t off) { return off ^ ((off >> 3) & 0x70); }

__device__ __forceinline__ void split_write(bf16* hi, bf16* lo, size_t o, float v) {
    bf16 h = __float2bfloat16(v);
    hi[o] = h;
    lo[o] = __float2bfloat16(v - __bfloat162float(h));
}

// ---------------- weight transpose + split ----------------
__global__ __launch_bounds__(256)
void transpose_convert(const float* __restrict__ in, bf16* __restrict__ hi, bf16* __restrict__ lo,
                       int R, int C)
{
    __shared__ float t[32][33];
    const int c0 = blockIdx.x * 32, r0 = blockIdx.y * 32;
    const int tx = threadIdx.x & 31, ty = threadIdx.x >> 5;
    #pragma unroll
    for (int i = 0; i < 32; i += 8)
        t[ty + i][tx] = in[(size_t)(r0 + ty + i) * C + c0 + tx];
    __syncthreads();
    #pragma unroll
    for (int i = 0; i < 32; i += 8)
        split_write(hi, lo, (size_t)(c0 + ty + i) * R + r0 + tx, t[tx][ty + i]);
}

// ---------------- elementwise fp32 -> hi/lo ----------------
__global__ __launch_bounds__(256)
void split_kernel(const float* __restrict__ in, bf16* __restrict__ hi, bf16* __restrict__ lo, size_t n)
{
    size_t i = (size_t)blockIdx.x * 1024 + threadIdx.x;
    #pragma unroll
    for (int j = 0; j < 4; j++) {
        size_t o = i + (size_t)j * 256;
        if (o < n) split_write(hi, lo, o, in[o]);
    }
}

// ---------------- bf16x3 mma.sync GEMM ----------------
// D = scale * A @ B^T (+bias/epilogue);  A,B bf16 hi/lo, K-major rows.
// CTA tile 256x128, 8 warps of 64x64, K-chunk 64, double buffered.
enum { EP_PLAIN=0, EP_QK=1, EP_VT=2, EP_MERGE=3, EP_RES=4, EP_GELU=5 };

#define ST_AH 0
#define ST_AL 32768
#define ST_BH 65536
#define ST_BL 81920
#define STAGE 98304
#define SMEM_DYN (2*STAGE + 1024)

template<int MODE>
__global__ __launch_bounds__(256)
void tc_gemm(const bf16* __restrict__ Ahi, const bf16* __restrict__ Alo,
             const bf16* __restrict__ Bhi, const bf16* __restrict__ Blo,
             const float* __restrict__ bias, const float* __restrict__ res,
             void* __restrict__ O0, void* __restrict__ O1,
             int M, int N, int K, float scale, long sA, long sB)
{
    extern __shared__ char dsm[];
    const uint32_t sbase = smem_u32(dsm);
    const uint32_t tile0 = (sbase + 1023u) & ~1023u;

    const int tid = threadIdx.x, warp = tid >> 5, lane = tid & 31;
    const int wm = warp >> 1;       // 0..3 -> m offset 64
    const int wn = warp & 1;        // 0..1 -> n offset 64
    const int bz = blockIdx.z;
    const int bm = blockIdx.y * 256, bn = blockIdx.x * 128;

    const bf16* Ah_g = Ahi + (size_t)bz * sA;
    const bf16* Al_g = Alo + (size_t)bz * sA;
    const bf16* Bh_g = Bhi + (size_t)bz * sB;
    const bf16* Bl_g = Blo + (size_t)bz * sB;

    float acc[4][8][4];
    #pragma unroll
    for (int i = 0; i < 4; i++)
        #pragma unroll
        for (int j = 0; j < 8; j++)
            #pragma unroll
            for (int p = 0; p < 4; p++) acc[i][j][p] = 0.f;

    const int NIT = K >> 6;

    auto load_chunk = [&](int stage, int k0) {
        const uint32_t st = tile0 + (uint32_t)stage * STAGE;
        // A hi/lo: 256 rows x 8 chunks of 16B
        #pragma unroll
        for (int i = 0; i < 8; i++) {
            const int idx = i * 256 + tid;
            const int r = idx >> 3, c = idx & 7;
            const uint32_t so = swz((uint32_t)(r * 128 + c * 16));
            cp16(st + ST_AH + so, Ah_g + (size_t)(bm + r) * K + k0 + c * 8);
            cp16(st + ST_AL + so, Al_g + (size_t)(bm + r) * K + k0 + c * 8);
        }
        // B hi/lo: 128 rows x 8 chunks
        #pragma unroll
        for (int i = 0; i < 4; i++) {
            const int idx = i * 256 + tid;
            const int r = idx >> 3, c = idx & 7;
            const uint32_t so = swz((uint32_t)(r * 128 + c * 16));
            cp16(st + ST_BH + so, Bh_g + (size_t)(bn + r) * K + k0 + c * 8);
            cp16(st + ST_BL + so, Bl_g + (size_t)(bn + r) * K + k0 + c * 8);
        }
        cp_commit();
    };

    load_chunk(0, 0);
    if (NIT > 1) load_chunk(1, 64);

    const uint32_t lrow = lane & 15;
    const uint32_t lkb  = (lane >> 4) * 16;   // byte offset for k+8 group

    for (int it = 0; it < NIT; it++) {
        const int cur = it & 1;
        if (it + 1 < NIT) cp_wait<1>(); else cp_wait<0>();
        __syncthreads();

        const uint32_t st = tile0 + (uint32_t)cur * STAGE;

        #pragma unroll
        for (int ks = 0; ks < 4; ks++) {
            const uint32_t kb = (uint32_t)ks * 32 + lkb;
            uint32_t ah[4][4], al[4][4], bh[4][4], bl[4][4];
            #pragma unroll
            for (int mt = 0; mt < 4; mt++) {
                const uint32_t off = (uint32_t)((wm * 64 + mt * 16 + lrow) * 128) + kb;
                const uint32_t so = swz(off);
                ldsm4(ah[mt], st + ST_AH + so);
                ldsm4(al[mt], st + ST_AL + so);
            }
            #pragma unroll
            for (int g = 0; g < 4; g++) {
                const uint32_t off = (uint32_t)((wn * 64 + g * 16 + lrow) * 128) + kb;
                const uint32_t so = swz(off);
                ldsm4(bh[g], st + ST_BH + so);
                ldsm4(bl[g], st + ST_BL + so);
            }
            #pragma unroll
            for (int mt = 0; mt < 4; mt++)
                #pragma unroll
                for (int nt = 0; nt < 8; nt++) {
                    const int g = nt >> 1, s2 = nt & 1;
                    uint32_t bhf[2] = { bh[g][s2], bh[g][s2 + 2] };
                    uint32_t blf[2] = { bl[g][s2], bl[g][s2 + 2] };
                    mma16816(acc[mt][nt], ah[mt], bhf);
                    mma16816(acc[mt][nt], ah[mt], blf);
                    mma16816(acc[mt][nt], al[mt], bhf);
                }
        }
        __syncthreads();
        if (it + 2 < NIT) load_chunk(cur, (it + 2) * 64);
    }

    // ---- epilogue ----
    #pragma unroll
    for (int mt = 0; mt < 4; mt++) {
        const int m0 = bm + wm * 64 + mt * 16 + (lane >> 2);
        #pragma unroll
        for (int nt = 0; nt < 8; nt++) {
            const int n0 = bn + wn * 64 + nt * 8 + (lane & 3) * 2;
            #pragma unroll
            for (int i = 0; i < 4; i++) {
                const int m = m0 + ((i >= 2) ? 8 : 0);
                const int n = n0 + (i & 1);
                float v = acc[mt][nt][i] * scale;

                if (MODE == EP_PLAIN) {
                    ((float*)O0)[(size_t)bz * ((size_t)M * N) + (size_t)m * N + n] = v;
                } else if (MODE == EP_QK) {
                    v += bias[n];
                    const int b = m >> 11, nn = m & (SEQ - 1);
                    const int h = n >> 7,  d = n & (HD - 1);
                    split_write((bf16*)O0, (bf16*)O1,
                                (((size_t)(b * HEADS + h)) * SEQ + nn) * HD + d, v);
                } else if (MODE == EP_VT) {
                    v += bias[n];
                    const int b = m >> 11, nn = m & (SEQ - 1);
                    const int h = n >> 7,  d = n & (HD - 1);
                    split_write((bf16*)O0, (bf16*)O1,
                                (((size_t)(b * HEADS + h)) * HD + d) * SEQ + nn, v);
                } else if (MODE == EP_MERGE) {
                    const int b = bz >> 4, h = bz & 15;
                    split_write((bf16*)O0, (bf16*)O1,
                                ((size_t)(b * SEQ + m)) * EMBED + h * HD + n, v);
                } else if (MODE == EP_RES) {
                    v += bias[n] + res[(size_t)m * N + n];
                    ((float*)O0)[(size_t)m * N + n] = v;
                } else { // EP_GELU
                    v += bias[n];
                    v = 0.5f * v * (1.f + erff(v * 0.70710678118654752f));
                    split_write((bf16*)O0, (bf16*)O1, (size_t)m * N + n, v);
                }
            }
        }
    }
}

// ---------------- softmax: fp32 in -> hi/lo bf16 out ----------------
__global__ __launch_bounds__(256)
void softmax_kernel(const float* __restrict__ S, bf16* __restrict__ Phi, bf16* __restrict__ Plo)
{
    __shared__ float red[256];
    const size_t row = blockIdx.x;
    const float* p = S + row * (size_t)SEQ;
    const int tid = threadIdx.x;

    float v[8];
    float lmax = -1e30f;
    #pragma unroll
    for (int i = 0; i < 8; i++) { v[i] = p[tid + i*256]; lmax = fmaxf(lmax, v[i]); }
    red[tid] = lmax; __syncthreads();
    for (int s = 128; s > 0; s >>= 1) { if (tid < s) red[tid] = fmaxf(red[tid], red[tid+s]); __syncthreads(); }
    const float m = red[0]; __syncthreads();

    float lsum = 0.f;
    #pragma unroll
    for (int i = 0; i < 8; i++) { v[i] = expf(v[i] - m); lsum += v[i]; }
    red[tid] = lsum; __syncthreads();
    for (int s = 128; s > 0; s >>= 1) { if (tid < s) red[tid] += red[tid+s]; __syncthreads(); }
    const float inv = 1.f / red[0];

    #pragma unroll
    for (int i = 0; i < 8; i++)
        split_write(Phi, Plo, row * (size_t)SEQ + tid + i*256, v[i] * inv);
}

// ---------------- LayerNorm ----------------
template<int BF>
__global__ __launch_bounds__(256)
void ln_kernel(const float* __restrict__ in, const float* __restrict__ g,
               const float* __restrict__ b, float* __restrict__ outf,
               bf16* __restrict__ ohi, bf16* __restrict__ olo)
{
    __shared__ float r1[256], r2[256];
    const size_t row = blockIdx.x;
    const float* p = in + row * (size_t)EMBED;
    const int tid = threadIdx.x;

    float v[8];
    float s = 0.f, ss = 0.f;
    #pragma unroll
    for (int i = 0; i < 8; i++) { v[i] = p[tid + i*256]; s += v[i]; ss += v[i]*v[i]; }
    r1[tid] = s; r2[tid] = ss; __syncthreads();
    for (int st = 128; st > 0; st >>= 1) {
        if (tid < st) { r1[tid] += r1[tid+st]; r2[tid] += r2[tid+st]; }
        __syncthreads();
    }
    const float mu  = r1[0] * (1.f / EMBED);
    const float var = r2[0] * (1.f / EMBED) - mu * mu;
    const float rs  = rsqrtf(var + LN_EPS);

    #pragma unroll
    for (int i = 0; i < 8; i++) {
        const int c = tid + i*256;
        const float o = (v[i] - mu) * rs * g[c] + b[c];
        outf[row * (size_t)EMBED + c] = o;
        if (BF) split_write(ohi, olo, row * (size_t)EMBED + c, o);
    }
}

// ---------------- launch ----------------
extern "C" void kernel_launch(void* const* d_in, const int* in_sizes, int n_in,
                              void* d_out, int out_size)
{
    const float* x   = (const float*)d_in[0];
    const float* Wq  = (const float*)d_in[1];
    const float* bq  = (const float*)d_in[2];
    const float* Wk  = (const float*)d_in[3];
    const float* bk  = (const float*)d_in[4];
    const float* Wv  = (const float*)d_in[5];
    const float* bv  = (const float*)d_in[6];
    const float* Wo  = (const float*)d_in[7];
    const float* bo  = (const float*)d_in[8];
    const float* g1  = (const float*)d_in[9];
    const float* b1  = (const float*)d_in[10];
    const float* g2  = (const float*)d_in[11];
    const float* b2  = (const float*)d_in[12];
    const float* W1  = (const float*)d_in[13];
    const float* bf1 = (const float*)d_in[14];
    const float* W2  = (const float*)d_in[15];
    const float* bf2 = (const float*)d_in[16];
    float* out = (float*)d_out;

    bf16 *xhi,*xlo,*qhi,*qlo,*khi,*klo,*vthi,*vtlo,*shi,*slo,*aohi,*aolo,*hhi,*hlo,*f1hi,*f1lo;
    bf16 *wqh,*wql,*wkh,*wkl,*wvh,*wvl,*woh,*wol,*w1h,*w1l,*w2h,*w2l;
    float *s, *t1, *h;
    cudaGetSymbolAddress((void**)&xhi, g_xhi); cudaGetSymbolAddress((void**)&xlo, g_xlo);
    cudaGetSymbolAddress((void**)&qhi, g_qhi); cudaGetSymbolAddress((void**)&qlo, g_qlo);
    cudaGetSymbolAddress((void**)&khi, g_khi); cudaGetSymbolAddress((void**)&klo, g_klo);
    cudaGetSymbolAddress((void**)&vthi,g_vthi);cudaGetSymbolAddress((void**)&vtlo,g_vtlo);
    cudaGetSymbolAddress((void**)&s,   g_s);
    cudaGetSymbolAddress((void**)&shi, g_shi); cudaGetSymbolAddress((void**)&slo, g_slo);
    cudaGetSymbolAddress((void**)&aohi,g_aohi);cudaGetSymbolAddress((void**)&aolo,g_aolo);
    cudaGetSymbolAddress((void**)&t1,  g_t1);  cudaGetSymbolAddress((void**)&h,   g_h);
    cudaGetSymbolAddress((void**)&hhi, g_hhi); cudaGetSymbolAddress((void**)&hlo, g_hlo);
    cudaGetSymbolAddress((void**)&f1hi,g_f1hi);cudaGetSymbolAddress((void**)&f1lo,g_f1lo);
    cudaGetSymbolAddress((void**)&wqh, g_wqh); cudaGetSymbolAddress((void**)&wql, g_wql);
    cudaGetSymbolAddress((void**)&wkh, g_wkh); cudaGetSymbolAddress((void**)&wkl, g_wkl);
    cudaGetSymbolAddress((void**)&wvh, g_wvh); cudaGetSymbolAddress((void**)&wvl, g_wvl);
    cudaGetSymbolAddress((void**)&woh, g_woh); cudaGetSymbolAddress((void**)&wol, g_wol);
    cudaGetSymbolAddress((void**)&w1h, g_w1h); cudaGetSymbolAddress((void**)&w1l, g_w1l);
    cudaGetSymbolAddress((void**)&w2h, g_w2h); cudaGetSymbolAddress((void**)&w2l, g_w2l);

    cudaFuncSetAttribute(tc_gemm<EP_PLAIN>, cudaFuncAttributeMaxDynamicSharedMemorySize, SMEM_DYN);
    cudaFuncSetAttribute(tc_gemm<EP_QK>,    cudaFuncAttributeMaxDynamicSharedMemorySize, SMEM_DYN);
    cudaFuncSetAttribute(tc_gemm<EP_VT>,    cudaFuncAttributeMaxDynamicSharedMemorySize, SMEM_DYN);
    cudaFuncSetAttribute(tc_gemm<EP_MERGE>, cudaFuncAttributeMaxDynamicSharedMemorySize, SMEM_DYN);
    cudaFuncSetAttribute(tc_gemm<EP_RES>,   cudaFuncAttributeMaxDynamicSharedMemorySize, SMEM_DYN);
    cudaFuncSetAttribute(tc_gemm<EP_GELU>,  cudaFuncAttributeMaxDynamicSharedMemorySize, SMEM_DYN);

    const float att_scale = 0.08838834764831845f; // 1/sqrt(128)

    // input + weight prep
    split_kernel<<<(TOKENS*(size_t)EMBED + 1023)/1024, 256>>>(x, xhi, xlo, (size_t)TOKENS*EMBED);
    dim3 tb(256);
    transpose_convert<<<dim3(EMBED/32, EMBED/32), tb>>>(Wq, wqh, wql, EMBED, EMBED);
    transpose_convert<<<dim3(EMBED/32, EMBED/32), tb>>>(Wk, wkh, wkl, EMBED, EMBED);
    transpose_convert<<<dim3(EMBED/32, EMBED/32), tb>>>(Wv, wvh, wvl, EMBED, EMBED);
    transpose_convert<<<dim3(EMBED/32, EMBED/32), tb>>>(Wo, woh, wol, EMBED, EMBED);
    transpose_convert<<<dim3(DFF/32,   EMBED/32), tb>>>(W1, w1h, w1l, EMBED, DFF);
    transpose_convert<<<dim3(EMBED/32, DFF/32),   tb>>>(W2, w2h, w2l, DFF,   EMBED);

    // QKV
    dim3 gQKV(EMBED/128, TOKENS/256, 1);
    tc_gemm<EP_QK><<<gQKV, 256, SMEM_DYN>>>(xhi, xlo, wqh, wql, bq, nullptr, qhi, qlo, TOKENS, EMBED, EMBED, 1.f, 0, 0);
    tc_gemm<EP_QK><<<gQKV, 256, SMEM_DYN>>>(xhi, xlo, wkh, wkl, bk, nullptr, khi, klo, TOKENS, EMBED, EMBED, 1.f, 0, 0);
    tc_gemm<EP_VT><<<gQKV, 256, SMEM_DYN>>>(xhi, xlo, wvh, wvl, bv, nullptr, vthi, vtlo, TOKENS, EMBED, EMBED, 1.f, 0, 0);

    // scores = scale * Q @ K^T
    dim3 gS(SEQ/128, SEQ/256, BATCH*HEADS);
    tc_gemm<EP_PLAIN><<<gS, 256, SMEM_DYN>>>(qhi, qlo, khi, klo, nullptr, nullptr, s, nullptr,
                                             SEQ, SEQ, HD, att_scale, (long)SEQ*HD, (long)SEQ*HD);
    softmax_kernel<<<BATCH*HEADS*SEQ, 256>>>(s, shi, slo);

    // O = P @ V^T
    dim3 gPV(1, SEQ/256, BATCH*HEADS);
    tc_gemm<EP_MERGE><<<gPV, 256, SMEM_DYN>>>(shi, slo, vthi, vtlo, nullptr, nullptr, aohi, aolo,
                                              SEQ, HD, SEQ, 1.f, (long)SEQ*SEQ, (long)HD*SEQ);

    // out-proj + residual, LN1
    dim3 gWo(EMBED/128, TOKENS/256, 1);
    tc_gemm<EP_RES><<<gWo, 256, SMEM_DYN>>>(aohi, aolo, woh, wol, bo, x, t1, nullptr, TOKENS, EMBED, EMBED, 1.f, 0, 0);
    ln_kernel<1><<<TOKENS, 256>>>(t1, g1, b1, h, hhi, hlo);

    // FFN
    dim3 gF1(DFF/128, TOKENS/256, 1);
    tc_gemm<EP_GELU><<<gF1, 256, SMEM_DYN>>>(hhi, hlo, w1h, w1l, bf1, nullptr, f1hi, f1lo, TOKENS, DFF, EMBED, 1.f, 0, 0);
    dim3 gF2(EMBED/128, TOKENS/256, 1);
    tc_gemm<EP_RES><<<gF2, 256, SMEM_DYN>>>(f1hi, f1lo, w2h, w2l, bf2, h, t1, nullptr, TOKENS, EMBED, DFF, 1.f, 0, 0);

    ln_kernel<0><<<TOKENS, 256>>>(t1, g2, b2, out, nullptr, nullptr);
}